// round 13
// baseline (speedup 1.0000x reference)
#include <cuda_runtime.h>
#include <cstdint>
#include <cstddef>

typedef unsigned int u32;
typedef unsigned long long u64;

// ---------------- problem dims ----------------
#define B_DIM 4096
#define I_DIM 256
#define H_DIM 1024
#define O_DIM 4096   // 4*H
#define MPL   4      // bit planes

#define NW_IH (MPL * I_DIM * O_DIM)   // 4,194,304
#define NW_HH (MPL * H_DIM * O_DIM)   // 16,777,216
#define N_B   (MPL * O_DIM)           // 16,384
#define N_NIB_IN (B_DIM * I_DIM)      // 1,048,576
#define N_NIB_HX (B_DIM * H_DIM)      // 4,194,304

// ---------------- static device scratch (no allocations allowed) ----------------
// Weff stored plane-interleaved: [K][O][MPL]
__device__ float   g_weff_ih[(size_t)I_DIM * O_DIM * MPL];      // 16 MB
__device__ float   g_weff_hh[(size_t)H_DIM * O_DIM * MPL];      // 64 MB
__device__ float   g_bq_ih[N_B];
__device__ float   g_nb_ih[N_B];
__device__ float   g_bq_hh[N_B];
__device__ float   g_nb_hh[N_B];
__device__ uint8_t g_nib_in[(size_t)N_NIB_IN];                  // 1 MB
__device__ uint8_t g_nib_hx[(size_t)N_NIB_HX];                  // 4 MB
__device__ float   g_gates1[(size_t)B_DIM * O_DIM];             // 64 MB (part1, ih)
__device__ float   g_gates2[(size_t)B_DIM * O_DIM];             // 64 MB (part2, hh)
// enc(-inf) = 0x007FFFFF; atomicMax is idempotent across graph replays
__device__ unsigned g_max[4] = {0x007FFFFFu, 0x007FFFFFu, 0x007FFFFFu, 0x007FFFFFu};
__device__ unsigned g_tile = 0u;     // work queue cursor; k_lstm resets for next call

// ---------------- threefry2x32 (JAX-exact) ----------------
__host__ __device__ __forceinline__ void threefry2x32(u32 k0, u32 k1, u32 x0, u32 x1,
                                                      u32 &o0, u32 &o1) {
  u32 ks2 = k0 ^ k1 ^ 0x1BD11BDAu;
  x0 += k0; x1 += k1;
#define TF_ROT(r) { x0 += x1; x1 = (x1 << (r)) | (x1 >> (32 - (r))); x1 ^= x0; }
  TF_ROT(13) TF_ROT(15) TF_ROT(26) TF_ROT(6)   x0 += k1;  x1 += ks2 + 1u;
  TF_ROT(17) TF_ROT(29) TF_ROT(16) TF_ROT(24)  x0 += ks2; x1 += k0 + 2u;
  TF_ROT(13) TF_ROT(15) TF_ROT(26) TF_ROT(6)   x0 += k0;  x1 += k1 + 3u;
  TF_ROT(17) TF_ROT(29) TF_ROT(16) TF_ROT(24)  x0 += k1;  x1 += ks2 + 4u;
  TF_ROT(13) TF_ROT(15) TF_ROT(26) TF_ROT(6)   x0 += ks2; x1 += k0 + 5u;
#undef TF_ROT
  o0 = x0; o1 = x1;
}

// ---------------- XLA-exact f32 transcendentals (unfused rn mul/add) --------
__device__ __forceinline__ float xla_log1p(float x) {
  float u = __fadd_rn(x, 1.0f);
  if (u == 1.0f) return x;
  return __fmul_rn(__fdiv_rn(x, __fsub_rn(u, 1.0f)), logf(u));
}

__device__ __forceinline__ float xla_erfinv(float x) {
  float w = -xla_log1p(__fmul_rn(__fmul_rn(-1.0f, x), x));
  float p;
  if (w < 5.0f) {
    w = __fsub_rn(w, 2.5f);
    p = 2.81022636e-08f;
    p = __fadd_rn(__fmul_rn(p, w), 3.43273939e-07f);
    p = __fadd_rn(__fmul_rn(p, w), -3.5233877e-06f);
    p = __fadd_rn(__fmul_rn(p, w), -4.39150654e-06f);
    p = __fadd_rn(__fmul_rn(p, w), 0.00021858087f);
    p = __fadd_rn(__fmul_rn(p, w), -0.00125372503f);
    p = __fadd_rn(__fmul_rn(p, w), -0.00417768164f);
    p = __fadd_rn(__fmul_rn(p, w), 0.246640727f);
    p = __fadd_rn(__fmul_rn(p, w), 1.50140941f);
  } else {
    w = __fsub_rn(sqrtf(w), 3.0f);
    p = -0.000200214257f;
    p = __fadd_rn(__fmul_rn(p, w), 0.000100950558f);
    p = __fadd_rn(__fmul_rn(p, w), 0.00134934322f);
    p = __fadd_rn(__fmul_rn(p, w), -0.00367342844f);
    p = __fadd_rn(__fmul_rn(p, w), 0.00573950773f);
    p = __fadd_rn(__fmul_rn(p, w), -0.0076224613f);
    p = __fadd_rn(__fmul_rn(p, w), 0.00943887047f);
    p = __fadd_rn(__fmul_rn(p, w), 1.00167406f);
    p = __fadd_rn(__fmul_rn(p, w), 2.83297682f);
  }
  return __fmul_rn(p, x);
}

__device__ __forceinline__ float xla_tanh(float x) {
  float ax = fabsf(x);
  if (ax < 0.0004f) return x;
  float xc = fminf(fmaxf(x, -7.90531110763549805f), 7.90531110763549805f);
  float x2 = __fmul_rn(xc, xc);
  float p = -2.76076847742355e-16f;
  p = __fadd_rn(__fmul_rn(p, x2), 2.00018790482477e-13f);
  p = __fadd_rn(__fmul_rn(p, x2), -8.60467152213735e-11f);
  p = __fadd_rn(__fmul_rn(p, x2), 5.12229709037114e-08f);
  p = __fadd_rn(__fmul_rn(p, x2), 1.48572235717979e-05f);
  p = __fadd_rn(__fmul_rn(p, x2), 6.37261928875436e-04f);
  p = __fadd_rn(__fmul_rn(p, x2), 4.89352455891786e-03f);
  p = __fmul_rn(p, xc);
  float q = 1.19825839466702e-06f;
  q = __fadd_rn(__fmul_rn(q, x2), 1.18534705686654e-04f);
  q = __fadd_rn(__fmul_rn(q, x2), 2.26843463243900e-03f);
  q = __fadd_rn(__fmul_rn(q, x2), 4.89352518554385e-03f);
  return __fdiv_rn(p, q);
}

__device__ __forceinline__ float xla_logistic(float x) {
  return __fadd_rn(0.5f, __fmul_rn(0.5f, xla_tanh(__fmul_rn(0.5f, x))));
}

// bits -> N(0,1) exactly as jax.random.normal (float32 path)
__device__ __forceinline__ float bits_to_normal(u32 bits) {
  float u = __uint_as_float((bits >> 9) | 0x3F800000u) - 1.0f;   // [0,1)
  const float lo = __uint_as_float(0xBF7FFFFFu);                 // nextafter(-1,0)
  float v = __fadd_rn(__fmul_rn(u, 2.0f), lo);
  v = fmaxf(v, lo);
  return __fmul_rn(__uint_as_float(0x3FB504F3u) /*sqrt2*/, xla_erfinv(v));
}

// partitionable threefry random_bits: bits[j] = o0 ^ o1 of TF(key, 0, j)
__device__ __forceinline__ u32 jax_bits32(u32 k0, u32 k1, u32 j) {
  u32 o0, o1; threefry2x32(k0, k1, 0u, j, o0, o1);
  return o0 ^ o1;
}

// ---------------- float max encoding for atomicMax ----------------
__device__ __forceinline__ unsigned fenc(float f) {
  unsigned u = __float_as_uint(f);
  return (u & 0x80000000u) ? ~u : (u | 0x80000000u);
}
__device__ __forceinline__ float fdec(unsigned u) {
  return (u & 0x80000000u) ? __uint_as_float(u & 0x7FFFFFFFu) : __uint_as_float(~u);
}

// one launch, 4 reductions (y selects the array)
__global__ void k_max4(const float* __restrict__ wih, const float* __restrict__ whh,
                       const float* __restrict__ bih, const float* __restrict__ bhh) {
  int slot = blockIdx.y;
  const float* x = (slot == 0) ? wih : (slot == 1) ? whh : (slot == 2) ? bih : bhh;
  int n = (slot == 0) ? NW_IH : (slot == 1) ? NW_HH : N_B;
  float m = -__int_as_float(0x7F800000);
  for (int i = blockIdx.x * blockDim.x + threadIdx.x; i < n; i += gridDim.x * blockDim.x)
    m = fmaxf(m, x[i]);
#pragma unroll
  for (int o = 16; o; o >>= 1) m = fmaxf(m, __shfl_xor_sync(0xFFFFFFFFu, m, o));
  if ((threadIdx.x & 31) == 0) atomicMax(&g_max[slot], fenc(m));
}

// quant(x, 8, 1.0) for weights
__device__ __forceinline__ float quant_w(float x) {
  float xs = fminf(fmaxf(x, -0.9921875f), 0.9921875f);
  return __fmul_rn(__fdiv_rn(rintf(__fmul_rn(xs, 128.0f)), 128.0f), 1.0f);
}

// Weff[k][o][m] = quant(W[m][k][o]) + normal(ctr = src linear)*wmax*0.1
// Both matrices in one launch: j < NW_IH -> ih, else hh.
__global__ void k_build_w_all(const float* __restrict__ Wih, const float* __restrict__ Whh,
                              u32 ka0, u32 ka1, u32 kb0, u32 kb1) {
  int j = blockIdx.x * blockDim.x + threadIdx.x;
  const float* W; float* dst; int K; u32 kk0, kk1; float wmax; int jj;
  if (j < NW_IH) {
    W = Wih; dst = g_weff_ih; K = I_DIM; kk0 = ka0; kk1 = ka1;
    wmax = fdec(g_max[0]); jj = j;
  } else {
    jj = j - NW_IH;
    if (jj >= NW_HH) return;
    W = Whh; dst = g_weff_hh; K = H_DIM; kk0 = kb0; kk1 = kb1;
    wmax = fdec(g_max[1]);
  }
  int k = jj >> 14;                 // O_DIM*MPL = 16384
  int rem = jj & 16383;
  int o = rem >> 2, m = rem & 3;
  u32 src = (u32)((m * K + k) * O_DIM + o);        // source linear = PRNG counter
  float nr = bits_to_normal(jax_bits32(kk0, kk1, src));
  dst[jj] = __fadd_rn(quant_w(W[src]), __fmul_rn(__fmul_rn(nr, wmax), 0.1f));
}

// nibbles (both branches) + biases (both branches), one launch.
__global__ void k_prep(const float* __restrict__ input, const float* __restrict__ hx,
                       const float* __restrict__ Bih, const float* __restrict__ Bhh,
                       const float* __restrict__ a1P, const float* __restrict__ a11P,
                       u32 kbi0, u32 kbi1, u32 kbh0, u32 kbh1) {
  int i = blockIdx.x * blockDim.x + threadIdx.x;
  float a1 = *a1P;
  if (i < N_NIB_IN) {
    float a = a1, off = a1;
    float t = __fdiv_rn(__fadd_rn(fminf(fmaxf(input[i], -a), a), off), __fmul_rn(a, 2.0f));
    g_nib_in[i] = (uint8_t)(((int)rintf(__fmul_rn(15.0f, t))) & 15);
  } else if (i < N_NIB_IN + N_NIB_HX) {
    int idx = i - N_NIB_IN;
    float a = *a11P, off = a1;                    // '+ a1' quirk preserved
    float t = __fdiv_rn(__fadd_rn(fminf(fmaxf(hx[idx], -a), a), off), __fmul_rn(a, 2.0f));
    g_nib_hx[idx] = (uint8_t)(((int)rintf(__fmul_rn(15.0f, t))) & 15);
  } else if (i < N_NIB_IN + N_NIB_HX + N_B) {
    int j = i - N_NIB_IN - N_NIB_HX;
    float bmax = fdec(g_max[2]);
    g_bq_ih[j] = quant_w(Bih[j]);
    g_nb_ih[j] = __fmul_rn(__fmul_rn(bits_to_normal(jax_bits32(kbi0, kbi1, (u32)j)), bmax), 0.1f);
  } else {
    int j = i - N_NIB_IN - N_NIB_HX - N_B;
    if (j >= N_B) return;
    float bmax = fdec(g_max[3]);
    g_bq_hh[j] = quant_w(Bhh[j]);
    g_nb_hh[j] = __fmul_rn(__fmul_rn(bits_to_normal(jax_bits32(kbh0, kbh1, (u32)j)), bmax), 0.1f);
  }
}

// ---------------- persistent GEMM (both branches, one kernel) ----------------
// fma.rn.f32x2 lanes = plane pairs; per-lane acc = rn(w*mask + acc).
// Masks computed in ALU: (byte & (1<<p)) * (0x3F800000 >> p) is EXACT
// (0x3F800000 has 23 trailing zeros, p <= 3) -> identical 1.0f/0.0f values
// to the old LUT -> bit-identical accumulation chain.
#define BM 64
#define BN 64
#define KC 32
#define N_TILES_HH 4096
#define N_TILES_ALL 8192
#define GRID_GEMM 304               // GB300: 152 SMs x 2 blocks/SM

__device__ __forceinline__ void fma2(u64 &acc, u64 w, u64 m) {
  asm volatile("fma.rn.f32x2 %0, %1, %2, %0;" : "+l"(acc) : "l"(w), "l"(m));
}
__device__ __forceinline__ void lds_v2u64(u64 &a, u64 &b, u32 addr) {
  asm volatile("ld.shared.v2.b64 {%0,%1}, [%2];" : "=l"(a), "=l"(b) : "r"(addr));
}
__device__ __forceinline__ void unpack2(u64 v, float &lo, float &hi) {
  u32 l, h;
  asm volatile("mov.b64 {%0,%1}, %2;" : "=r"(l), "=r"(h) : "l"(v));
  lo = __uint_as_float(l); hi = __uint_as_float(h);
}
__device__ __forceinline__ u64 mkpair(u32 lo, u32 hi) {
  u64 v; asm("mov.b64 %0, {%1,%2};" : "=l"(v) : "r"(lo), "r"(hi)); return v;
}

__launch_bounds__(256, 2)
__global__ void k_gemm_all(const float* __restrict__ a1P, const float* __restrict__ a11P) {
  __shared__ __align__(16) float sW[KC][BN * MPL];   // 32 KB, [k][o*4+m]
  __shared__ u32 sA[BM][KC / 4];                     // 2 KB
  __shared__ u32 sTile;

  int tid = threadIdx.x;
  int tx = tid & 15, ty = tid >> 4;
  int rowBase = ty * 4;

  u32 sWb = (u32)__cvta_generic_to_shared(sW);

  while (true) {
    if (tid == 0) sTile = atomicAdd(&g_tile, 1u);
    __syncthreads();                 // orders prev-tile smem reuse
    u32 t = sTile;
    if (t >= N_TILES_ALL) break;

    // hh tiles first (big), then ih (small) for a short ragged tail
    bool hh = (t < N_TILES_HH);
    u32 t2 = hh ? t : (t - N_TILES_HH);
    int K = hh ? H_DIM : I_DIM;
    const float* __restrict__ Wg = hh ? g_weff_hh : g_weff_ih;   // [K][O][MPL]
    const float* __restrict__ bq = hh ? g_bq_hh : g_bq_ih;
    const float* __restrict__ nb = hh ? g_nb_hh : g_nb_ih;
    const uint8_t* __restrict__ nibp = hh ? g_nib_hx : g_nib_in;
    float* __restrict__ gout = hh ? g_gates2 : g_gates1;
    float a = hh ? *a11P : *a1P;

    int ob = (int)(t2 & 63) * BN;
    int bb = (int)(t2 >> 6) * BM;

    u64 acc[4][4][2];   // [row][col][plane-pair]
#pragma unroll
    for (int r = 0; r < 4; ++r)
#pragma unroll
      for (int c = 0; c < 4; ++c) { acc[r][c][0] = 0ull; acc[r][c][1] = 0ull; }

    for (int k0 = 0; k0 < K; k0 += KC) {
#pragma unroll
      for (int tt = 0; tt < 2; ++tt) {            // A tile: 64 rows x 8 u32
        int idx = tid + tt * 256;
        int r = idx >> 3, k4 = idx & 7;
        sA[r][k4] = *(const u32*)(nibp + (size_t)(bb + r) * K + k0 + k4 * 4);
      }
#pragma unroll
      for (int tt = 0; tt < 8; ++tt) {            // W tile: 2048 contiguous float4
        int idx = tid + tt * 256;
        int k = idx >> 6, w4 = idx & 63;
        *(float4*)&sW[k][w4 * 4] =
            *(const float4*)(Wg + ((size_t)(k0 + k) * O_DIM + ob) * MPL + w4 * 4);
      }
      __syncthreads();

#pragma unroll 4
      for (int k4 = 0; k4 < KC / 4; ++k4) {
        u32 a0 = sA[rowBase + 0][k4];
        u32 a1 = sA[rowBase + 1][k4];
        u32 a2 = sA[rowBase + 2][k4];
        u32 a3 = sA[rowBase + 3][k4];
#pragma unroll
        for (int s = 0; s < 4; ++s) {
          int k = k4 * 4 + s;
          // masks from nibble bits (exact 1.0f/0.0f, no LDS)
          u64 mk[4][2];
          mk[0][0] = mkpair((a0 & 8u) * 0x07F00000u, (a0 & 4u) * 0x0FE00000u);
          mk[0][1] = mkpair((a0 & 2u) * 0x1FC00000u, (a0 & 1u) * 0x3F800000u);
          mk[1][0] = mkpair((a1 & 8u) * 0x07F00000u, (a1 & 4u) * 0x0FE00000u);
          mk[1][1] = mkpair((a1 & 2u) * 0x1FC00000u, (a1 & 1u) * 0x3F800000u);
          mk[2][0] = mkpair((a2 & 8u) * 0x07F00000u, (a2 & 4u) * 0x0FE00000u);
          mk[2][1] = mkpair((a2 & 2u) * 0x1FC00000u, (a2 & 1u) * 0x3F800000u);
          mk[3][0] = mkpair((a3 & 8u) * 0x07F00000u, (a3 & 4u) * 0x0FE00000u);
          mk[3][1] = mkpair((a3 & 2u) * 0x1FC00000u, (a3 & 1u) * 0x3F800000u);
          a0 >>= 8; a1 >>= 8; a2 >>= 8; a3 >>= 8;
#pragma unroll
          for (int c = 0; c < 4; ++c) {
            u64 w0, w1;
            u32 wad = sWb + (u32)(k * (BN * MPL * 4)) + (u32)((tx + 16 * c) * 16);
            lds_v2u64(w0, w1, wad);
#pragma unroll
            for (int r = 0; r < 4; ++r) {
              fma2(acc[r][c][0], w0, mk[r][0]);
              fma2(acc[r][c][1], w1, mk[r][1]);
            }
          }
        }
      }
      __syncthreads();
    }

    // epilogue: threshold per plane, beta-recombine, scale -> its own buffer
    float twoa = __fmul_rn(a, 2.0f);
    const float beta[MPL] = {8.0f / 15.0f, 4.0f / 15.0f, 2.0f / 15.0f, 1.0f / 15.0f};
#pragma unroll
    for (int r = 0; r < 4; ++r) {
#pragma unroll
      for (int c = 0; c < 4; ++c) {
        int b = bb + rowBase + r, o = ob + tx + 16 * c;
        float sv[4];
        unpack2(acc[r][c][0], sv[0], sv[1]);
        unpack2(acc[r][c][1], sv[2], sv[3]);
        float p = 0.0f;
#pragma unroll
        for (int m = 0; m < MPL; ++m) {
          float s = __fadd_rn(__fadd_rn(sv[m], bq[m * O_DIM + o]), nb[m * O_DIM + o]);
          p = __fadd_rn(p, (s > 0.5f) ? beta[m] : 0.0f);
        }
        gout[(size_t)b * O_DIM + o] = __fsub_rn(__fmul_rn(p, twoa), a);
      }
    }
  }
}

// ---------------- quantized LSTM pointwise tail ----------------
__device__ __forceinline__ float pactf(float x, float a) { return fminf(fmaxf(x, -a), a); }
__device__ __forceinline__ float quant8(float x, float r) {
  float xs = __fdiv_rn(x, r);
  xs = fminf(fmaxf(xs, -0.9921875f), 0.9921875f);
  return __fmul_rn(__fdiv_rn(rintf(__fmul_rn(xs, 128.0f)), 128.0f), r);
}

__global__ void k_lstm(const float* __restrict__ cx, float* __restrict__ out,
                       const float* a3, const float* a4, const float* a5, const float* a6,
                       const float* a7, const float* a8, const float* a9, const float* a10,
                       const float* a11) {
  int idx = blockIdx.x * blockDim.x + threadIdx.x;
  if (idx == 0) g_tile = 0u;          // reset work queue for the next graph replay
  if (idx >= B_DIM * H_DIM) return;
  int b = idx >> 10, h = idx & (H_DIM - 1);
  const float* g1 = g_gates1 + (size_t)b * O_DIM;
  const float* g2 = g_gates2 + (size_t)b * O_DIM;
  float gi = __fadd_rn(g1[h],        g2[h]);
  float gj = __fadd_rn(g1[h + 1024], g2[h + 1024]);
  float gf = __fadd_rn(g1[h + 2048], g2[h + 2048]);
  float go = __fadd_rn(g1[h + 3072], g2[h + 3072]);

  float v3 = *a3, v4 = *a4, v5 = *a5, v6 = *a6, v7 = *a7, v8 = *a8, v9 = *a9,
        v10 = *a10, v11 = *a11;
  float fg  = quant8(pactf(xla_logistic(gf), v3), v3);
  float ig  = quant8(pactf(xla_logistic(gi), v4), v4);
  float act = quant8(pactf(xla_tanh(gj), v5), v5);
  float og  = quant8(pactf(xla_logistic(go), v6), v6);
  float gated = quant8(pactf(__fmul_rn(cx[idx], fg), v7), v7);
  float actin = quant8(pactf(__fmul_rn(ig, act), v8), v8);
  float newc  = quant8(pactf(__fadd_rn(gated, actin), v9), v9);
  float actc  = quant8(pactf(xla_tanh(newc), v10), v10);
  float newh  = quant8(pactf(__fmul_rn(actc, og), v11), v11);
  out[idx] = newh;
  out[(size_t)B_DIM * H_DIM + idx] = newc;
}

// ---------------- host side ----------------
static void split2(const u32 k[2], u32 ka[2], u32 kb[2]) {
  threefry2x32(k[0], k[1], 0u, 0u, ka[0], ka[1]);
  threefry2x32(k[0], k[1], 0u, 1u, kb[0], kb[1]);
}

extern "C" void kernel_launch(void* const* d_in, const int* in_sizes, int n_in,
                              void* d_out, int out_size) {
  const float* input = (const float*)d_in[0];
  const float* hx    = (const float*)d_in[1];
  const float* cx    = (const float*)d_in[2];
  const float* wih   = (const float*)d_in[3];
  const float* whh   = (const float*)d_in[4];
  const float* bih   = (const float*)d_in[5];
  const float* bhh   = (const float*)d_in[6];
  const float* a1  = (const float*)d_in[7];
  const float* a3  = (const float*)d_in[8];
  const float* a4  = (const float*)d_in[9];
  const float* a5  = (const float*)d_in[10];
  const float* a6  = (const float*)d_in[11];
  const float* a7  = (const float*)d_in[12];
  const float* a8  = (const float*)d_in[13];
  const float* a9  = (const float*)d_in[14];
  const float* a10 = (const float*)d_in[15];
  const float* a11 = (const float*)d_in[16];

  // key(42) -> (k1,k2); k1 -> (kw_ih, kb_ih); k2 -> (kw_hh, kb_hh)   [fold-like]
  u32 root[2] = {0u, 42u}, K1[2], K2[2], KW1[2], KB1[2], KW2[2], KB2[2];
  split2(root, K1, K2);
  split2(K1, KW1, KB1);
  split2(K2, KW2, KB2);

  {
    dim3 g(512, 4);
    k_max4<<<g, 256>>>(wih, whh, bih, bhh);
  }

  k_build_w_all<<<(NW_IH + NW_HH + 255) / 256, 256>>>(wih, whh,
                                                      KW1[0], KW1[1], KW2[0], KW2[1]);
  {
    const int total = N_NIB_IN + N_NIB_HX + 2 * N_B;
    k_prep<<<(total + 255) / 256, 256>>>(input, hx, bih, bhh, a1, a11,
                                         KB1[0], KB1[1], KB2[0], KB2[1]);
  }

  // one persistent kernel: hh tiles (0..4095) then ih tiles (4096..8191)
  k_gemm_all<<<GRID_GEMM, 256>>>(a1, a11);

  k_lstm<<<(B_DIM * H_DIM + 255) / 256, 256>>>(cx, (float*)d_out,
                                               a3, a4, a5, a6, a7, a8, a9, a10, a11);
}

// round 15
// speedup vs baseline: 1.1821x; 1.1821x over previous
#include <cuda_runtime.h>
#include <cstdint>
#include <cstddef>

typedef unsigned int u32;
typedef unsigned long long u64;

// ---------------- problem dims ----------------
#define B_DIM 4096
#define I_DIM 256
#define H_DIM 1024
#define O_DIM 4096   // 4*H
#define MPL   4      // bit planes

#define NW_IH (MPL * I_DIM * O_DIM)   // 4,194,304
#define NW_HH (MPL * H_DIM * O_DIM)   // 16,777,216
#define N_B   (MPL * O_DIM)           // 16,384
#define N_NIB_IN (B_DIM * I_DIM)      // 1,048,576
#define N_NIB_HX (B_DIM * H_DIM)      // 4,194,304

// ---------------- static device scratch (no allocations allowed) ----------------
// Weff stored plane-interleaved: [K][O][MPL]
__device__ float   g_weff_ih[(size_t)I_DIM * O_DIM * MPL];      // 16 MB
__device__ float   g_weff_hh[(size_t)H_DIM * O_DIM * MPL];      // 64 MB
__device__ float   g_bq_ih[N_B];
__device__ float   g_nb_ih[N_B];
__device__ float   g_bq_hh[N_B];
__device__ float   g_nb_hh[N_B];
__device__ uint8_t g_nib_in[(size_t)N_NIB_IN];                  // 1 MB
__device__ uint8_t g_nib_hx[(size_t)N_NIB_HX];                  // 4 MB
__device__ float   g_gates1[(size_t)B_DIM * O_DIM];             // 64 MB (part1, ih)
__device__ float   g_gates2[(size_t)B_DIM * O_DIM];             // 64 MB (part2, hh)
// enc(-inf) = 0x007FFFFF; atomicMax is idempotent across graph replays
__device__ unsigned g_max[4] = {0x007FFFFFu, 0x007FFFFFu, 0x007FFFFFu, 0x007FFFFFu};
__device__ unsigned g_tile = 0u;     // work queue cursor; k_lstm resets for next call

// ---------------- threefry2x32 (JAX-exact) ----------------
__host__ __device__ __forceinline__ void threefry2x32(u32 k0, u32 k1, u32 x0, u32 x1,
                                                      u32 &o0, u32 &o1) {
  u32 ks2 = k0 ^ k1 ^ 0x1BD11BDAu;
  x0 += k0; x1 += k1;
#define TF_ROT(r) { x0 += x1; x1 = (x1 << (r)) | (x1 >> (32 - (r))); x1 ^= x0; }
  TF_ROT(13) TF_ROT(15) TF_ROT(26) TF_ROT(6)   x0 += k1;  x1 += ks2 + 1u;
  TF_ROT(17) TF_ROT(29) TF_ROT(16) TF_ROT(24)  x0 += ks2; x1 += k0 + 2u;
  TF_ROT(13) TF_ROT(15) TF_ROT(26) TF_ROT(6)   x0 += k0;  x1 += k1 + 3u;
  TF_ROT(17) TF_ROT(29) TF_ROT(16) TF_ROT(24)  x0 += k1;  x1 += ks2 + 4u;
  TF_ROT(13) TF_ROT(15) TF_ROT(26) TF_ROT(6)   x0 += ks2; x1 += k0 + 5u;
#undef TF_ROT
  o0 = x0; o1 = x1;
}

// ---------------- XLA-exact f32 transcendentals (unfused rn mul/add) --------
__device__ __forceinline__ float xla_log1p(float x) {
  float u = __fadd_rn(x, 1.0f);
  if (u == 1.0f) return x;
  return __fmul_rn(__fdiv_rn(x, __fsub_rn(u, 1.0f)), logf(u));
}

__device__ __forceinline__ float xla_erfinv(float x) {
  float w = -xla_log1p(__fmul_rn(__fmul_rn(-1.0f, x), x));
  float p;
  if (w < 5.0f) {
    w = __fsub_rn(w, 2.5f);
    p = 2.81022636e-08f;
    p = __fadd_rn(__fmul_rn(p, w), 3.43273939e-07f);
    p = __fadd_rn(__fmul_rn(p, w), -3.5233877e-06f);
    p = __fadd_rn(__fmul_rn(p, w), -4.39150654e-06f);
    p = __fadd_rn(__fmul_rn(p, w), 0.00021858087f);
    p = __fadd_rn(__fmul_rn(p, w), -0.00125372503f);
    p = __fadd_rn(__fmul_rn(p, w), -0.00417768164f);
    p = __fadd_rn(__fmul_rn(p, w), 0.246640727f);
    p = __fadd_rn(__fmul_rn(p, w), 1.50140941f);
  } else {
    w = __fsub_rn(sqrtf(w), 3.0f);
    p = -0.000200214257f;
    p = __fadd_rn(__fmul_rn(p, w), 0.000100950558f);
    p = __fadd_rn(__fmul_rn(p, w), 0.00134934322f);
    p = __fadd_rn(__fmul_rn(p, w), -0.00367342844f);
    p = __fadd_rn(__fmul_rn(p, w), 0.00573950773f);
    p = __fadd_rn(__fmul_rn(p, w), -0.0076224613f);
    p = __fadd_rn(__fmul_rn(p, w), 0.00943887047f);
    p = __fadd_rn(__fmul_rn(p, w), 1.00167406f);
    p = __fadd_rn(__fmul_rn(p, w), 2.83297682f);
  }
  return __fmul_rn(p, x);
}

__device__ __forceinline__ float xla_tanh(float x) {
  float ax = fabsf(x);
  if (ax < 0.0004f) return x;
  float xc = fminf(fmaxf(x, -7.90531110763549805f), 7.90531110763549805f);
  float x2 = __fmul_rn(xc, xc);
  float p = -2.76076847742355e-16f;
  p = __fadd_rn(__fmul_rn(p, x2), 2.00018790482477e-13f);
  p = __fadd_rn(__fmul_rn(p, x2), -8.60467152213735e-11f);
  p = __fadd_rn(__fmul_rn(p, x2), 5.12229709037114e-08f);
  p = __fadd_rn(__fmul_rn(p, x2), 1.48572235717979e-05f);
  p = __fadd_rn(__fmul_rn(p, x2), 6.37261928875436e-04f);
  p = __fadd_rn(__fmul_rn(p, x2), 4.89352455891786e-03f);
  p = __fmul_rn(p, xc);
  float q = 1.19825839466702e-06f;
  q = __fadd_rn(__fmul_rn(q, x2), 1.18534705686654e-04f);
  q = __fadd_rn(__fmul_rn(q, x2), 2.26843463243900e-03f);
  q = __fadd_rn(__fmul_rn(q, x2), 4.89352518554385e-03f);
  return __fdiv_rn(p, q);
}

__device__ __forceinline__ float xla_logistic(float x) {
  return __fadd_rn(0.5f, __fmul_rn(0.5f, xla_tanh(__fmul_rn(0.5f, x))));
}

// bits -> N(0,1) exactly as jax.random.normal (float32 path)
__device__ __forceinline__ float bits_to_normal(u32 bits) {
  float u = __uint_as_float((bits >> 9) | 0x3F800000u) - 1.0f;   // [0,1)
  const float lo = __uint_as_float(0xBF7FFFFFu);                 // nextafter(-1,0)
  float v = __fadd_rn(__fmul_rn(u, 2.0f), lo);
  v = fmaxf(v, lo);
  return __fmul_rn(__uint_as_float(0x3FB504F3u) /*sqrt2*/, xla_erfinv(v));
}

// partitionable threefry random_bits: bits[j] = o0 ^ o1 of TF(key, 0, j)
__device__ __forceinline__ u32 jax_bits32(u32 k0, u32 k1, u32 j) {
  u32 o0, o1; threefry2x32(k0, k1, 0u, j, o0, o1);
  return o0 ^ o1;
}

// ---------------- float max encoding for atomicMax ----------------
__device__ __forceinline__ unsigned fenc(float f) {
  unsigned u = __float_as_uint(f);
  return (u & 0x80000000u) ? ~u : (u | 0x80000000u);
}
__device__ __forceinline__ float fdec(unsigned u) {
  return (u & 0x80000000u) ? __uint_as_float(u & 0x7FFFFFFFu) : __uint_as_float(~u);
}

// one launch, 4 reductions (y selects the array)
__global__ void k_max4(const float* __restrict__ wih, const float* __restrict__ whh,
                       const float* __restrict__ bih, const float* __restrict__ bhh) {
  int slot = blockIdx.y;
  const float* x = (slot == 0) ? wih : (slot == 1) ? whh : (slot == 2) ? bih : bhh;
  int n = (slot == 0) ? NW_IH : (slot == 1) ? NW_HH : N_B;
  float m = -__int_as_float(0x7F800000);
  for (int i = blockIdx.x * blockDim.x + threadIdx.x; i < n; i += gridDim.x * blockDim.x)
    m = fmaxf(m, x[i]);
#pragma unroll
  for (int o = 16; o; o >>= 1) m = fmaxf(m, __shfl_xor_sync(0xFFFFFFFFu, m, o));
  if ((threadIdx.x & 31) == 0) atomicMax(&g_max[slot], fenc(m));
}

// quant(x, 8, 1.0) for weights
__device__ __forceinline__ float quant_w(float x) {
  float xs = fminf(fmaxf(x, -0.9921875f), 0.9921875f);
  return __fmul_rn(__fdiv_rn(rintf(__fmul_rn(xs, 128.0f)), 128.0f), 1.0f);
}

// Weff[k][o][m] = quant(W[m][k][o]) + normal(ctr = src linear)*wmax*0.1
// Both matrices in one launch: j < NW_IH -> ih, else hh.
__global__ void k_build_w_all(const float* __restrict__ Wih, const float* __restrict__ Whh,
                              u32 ka0, u32 ka1, u32 kb0, u32 kb1) {
  int j = blockIdx.x * blockDim.x + threadIdx.x;
  const float* W; float* dst; int K; u32 kk0, kk1; float wmax; int jj;
  if (j < NW_IH) {
    W = Wih; dst = g_weff_ih; K = I_DIM; kk0 = ka0; kk1 = ka1;
    wmax = fdec(g_max[0]); jj = j;
  } else {
    jj = j - NW_IH;
    if (jj >= NW_HH) return;
    W = Whh; dst = g_weff_hh; K = H_DIM; kk0 = kb0; kk1 = kb1;
    wmax = fdec(g_max[1]);
  }
  int k = jj >> 14;                 // O_DIM*MPL = 16384
  int rem = jj & 16383;
  int o = rem >> 2, m = rem & 3;
  u32 src = (u32)((m * K + k) * O_DIM + o);        // source linear = PRNG counter
  float nr = bits_to_normal(jax_bits32(kk0, kk1, src));
  dst[jj] = __fadd_rn(quant_w(W[src]), __fmul_rn(__fmul_rn(nr, wmax), 0.1f));
}

// nibbles (both branches) + biases (both branches), one launch.
__global__ void k_prep(const float* __restrict__ input, const float* __restrict__ hx,
                       const float* __restrict__ Bih, const float* __restrict__ Bhh,
                       const float* __restrict__ a1P, const float* __restrict__ a11P,
                       u32 kbi0, u32 kbi1, u32 kbh0, u32 kbh1) {
  int i = blockIdx.x * blockDim.x + threadIdx.x;
  float a1 = *a1P;
  if (i < N_NIB_IN) {
    float a = a1, off = a1;
    float t = __fdiv_rn(__fadd_rn(fminf(fmaxf(input[i], -a), a), off), __fmul_rn(a, 2.0f));
    g_nib_in[i] = (uint8_t)(((int)rintf(__fmul_rn(15.0f, t))) & 15);
  } else if (i < N_NIB_IN + N_NIB_HX) {
    int idx = i - N_NIB_IN;
    float a = *a11P, off = a1;                    // '+ a1' quirk preserved
    float t = __fdiv_rn(__fadd_rn(fminf(fmaxf(hx[idx], -a), a), off), __fmul_rn(a, 2.0f));
    g_nib_hx[idx] = (uint8_t)(((int)rintf(__fmul_rn(15.0f, t))) & 15);
  } else if (i < N_NIB_IN + N_NIB_HX + N_B) {
    int j = i - N_NIB_IN - N_NIB_HX;
    float bmax = fdec(g_max[2]);
    g_bq_ih[j] = quant_w(Bih[j]);
    g_nb_ih[j] = __fmul_rn(__fmul_rn(bits_to_normal(jax_bits32(kbi0, kbi1, (u32)j)), bmax), 0.1f);
  } else {
    int j = i - N_NIB_IN - N_NIB_HX - N_B;
    if (j >= N_B) return;
    float bmax = fdec(g_max[3]);
    g_bq_hh[j] = quant_w(Bhh[j]);
    g_nb_hh[j] = __fmul_rn(__fmul_rn(bits_to_normal(jax_bits32(kbh0, kbh1, (u32)j)), bmax), 0.1f);
  }
}

// ---------------- persistent GEMM (both branches, one kernel) ----------------
// fma.rn.f32x2 lanes = plane pairs; per-lane acc = rn(w*mask + acc).
// Masks generated on the ALU pipe: LOP3-with-predicate + SELP produce the
// exact constants 0x3F800000 (1.0f) / 0x00000000 (0.0f) -- identical values to
// the old LUT -> bit-identical accumulation chain. No IMAD (keeps fma pipe
// clear for FFMA2), no mask LDS (halves crossbar bytes).
#define BM 64
#define BN 64
#define KC 32
#define N_TILES_HH 4096
#define N_TILES_ALL 8192
#define GRID_GEMM 304               // GB300: 152 SMs x 2 blocks/SM

__device__ __forceinline__ void fma2(u64 &acc, u64 w, u64 m) {
  asm volatile("fma.rn.f32x2 %0, %1, %2, %0;" : "+l"(acc) : "l"(w), "l"(m));
}
__device__ __forceinline__ void lds_v2u64(u64 &a, u64 &b, u32 addr) {
  asm volatile("ld.shared.v2.b64 {%0,%1}, [%2];" : "=l"(a), "=l"(b) : "r"(addr));
}
__device__ __forceinline__ void unpack2(u64 v, float &lo, float &hi) {
  u32 l, h;
  asm volatile("mov.b64 {%0,%1}, %2;" : "=r"(l), "=r"(h) : "l"(v));
  lo = __uint_as_float(l); hi = __uint_as_float(h);
}

// mask pair from nibble bits 3,2 (lo word = bit3, hi word = bit2)
__device__ __forceinline__ u64 mask_hi(u32 av) {
  u64 out;
  asm("{\n\t"
      ".reg .pred p3, p2;\n\t"
      ".reg .b32 t3, t2, m3, m2;\n\t"
      "and.b32 t3, %1, 8;\n\t"
      "and.b32 t2, %1, 4;\n\t"
      "setp.ne.u32 p3, t3, 0;\n\t"
      "setp.ne.u32 p2, t2, 0;\n\t"
      "selp.b32 m3, 0x3F800000, 0, p3;\n\t"
      "selp.b32 m2, 0x3F800000, 0, p2;\n\t"
      "mov.b64 %0, {m3, m2};\n\t"
      "}" : "=l"(out) : "r"(av));
  return out;
}
// mask pair from nibble bits 1,0 (lo word = bit1, hi word = bit0)
__device__ __forceinline__ u64 mask_lo(u32 av) {
  u64 out;
  asm("{\n\t"
      ".reg .pred p1, p0;\n\t"
      ".reg .b32 t1, t0, m1, m0;\n\t"
      "and.b32 t1, %1, 2;\n\t"
      "and.b32 t0, %1, 1;\n\t"
      "setp.ne.u32 p1, t1, 0;\n\t"
      "setp.ne.u32 p0, t0, 0;\n\t"
      "selp.b32 m1, 0x3F800000, 0, p1;\n\t"
      "selp.b32 m0, 0x3F800000, 0, p0;\n\t"
      "mov.b64 %0, {m1, m0};\n\t"
      "}" : "=l"(out) : "r"(av));
  return out;
}

__launch_bounds__(256, 2)
__global__ void k_gemm_all(const float* __restrict__ a1P, const float* __restrict__ a11P) {
  __shared__ __align__(16) float sW[KC][BN * MPL];   // 32 KB, [k][o*4+m]
  __shared__ u32 sA[BM][KC / 4];                     // 2 KB
  __shared__ u32 sTile;

  int tid = threadIdx.x;
  int tx = tid & 15, ty = tid >> 4;
  int rowBase = ty * 4;

  u32 sWb = (u32)__cvta_generic_to_shared(sW);

  while (true) {
    if (tid == 0) sTile = atomicAdd(&g_tile, 1u);
    __syncthreads();                 // orders prev-tile smem reuse
    u32 t = sTile;
    if (t >= N_TILES_ALL) break;

    // hh tiles first (big), then ih (small) for a short ragged tail
    bool hh = (t < N_TILES_HH);
    u32 t2 = hh ? t : (t - N_TILES_HH);
    int K = hh ? H_DIM : I_DIM;
    const float* __restrict__ Wg = hh ? g_weff_hh : g_weff_ih;   // [K][O][MPL]
    const float* __restrict__ bq = hh ? g_bq_hh : g_bq_ih;
    const float* __restrict__ nb = hh ? g_nb_hh : g_nb_ih;
    const uint8_t* __restrict__ nibp = hh ? g_nib_hx : g_nib_in;
    float* __restrict__ gout = hh ? g_gates2 : g_gates1;
    float a = hh ? *a11P : *a1P;

    int ob = (int)(t2 & 63) * BN;
    int bb = (int)(t2 >> 6) * BM;

    u64 acc[4][4][2];   // [row][col][plane-pair]
#pragma unroll
    for (int r = 0; r < 4; ++r)
#pragma unroll
      for (int c = 0; c < 4; ++c) { acc[r][c][0] = 0ull; acc[r][c][1] = 0ull; }

    for (int k0 = 0; k0 < K; k0 += KC) {
#pragma unroll
      for (int tt = 0; tt < 2; ++tt) {            // A tile: 64 rows x 8 u32
        int idx = tid + tt * 256;
        int r = idx >> 3, k4 = idx & 7;
        sA[r][k4] = *(const u32*)(nibp + (size_t)(bb + r) * K + k0 + k4 * 4);
      }
#pragma unroll
      for (int tt = 0; tt < 8; ++tt) {            // W tile: 2048 contiguous float4
        int idx = tid + tt * 256;
        int k = idx >> 6, w4 = idx & 63;
        *(float4*)&sW[k][w4 * 4] =
            *(const float4*)(Wg + ((size_t)(k0 + k) * O_DIM + ob) * MPL + w4 * 4);
      }
      __syncthreads();

#pragma unroll 4
      for (int k4 = 0; k4 < KC / 4; ++k4) {
        u32 a0 = sA[rowBase + 0][k4];
        u32 a1 = sA[rowBase + 1][k4];
        u32 a2 = sA[rowBase + 2][k4];
        u32 a3 = sA[rowBase + 3][k4];
#pragma unroll
        for (int s = 0; s < 4; ++s) {
          int k = k4 * 4 + s;
          // masks from nibble bits via LOP3.pred + SELP (alu pipe, exact values)
          u64 mk[4][2];
          mk[0][0] = mask_hi(a0);  mk[0][1] = mask_lo(a0);
          mk[1][0] = mask_hi(a1);  mk[1][1] = mask_lo(a1);
          mk[2][0] = mask_hi(a2);  mk[2][1] = mask_lo(a2);
          mk[3][0] = mask_hi(a3);  mk[3][1] = mask_lo(a3);
          a0 >>= 8; a1 >>= 8; a2 >>= 8; a3 >>= 8;
#pragma unroll
          for (int c = 0; c < 4; ++c) {
            u64 w0, w1;
            u32 wad = sWb + (u32)(k * (BN * MPL * 4)) + (u32)((tx + 16 * c) * 16);
            lds_v2u64(w0, w1, wad);
#pragma unroll
            for (int r = 0; r < 4; ++r) {
              fma2(acc[r][c][0], w0, mk[r][0]);
              fma2(acc[r][c][1], w1, mk[r][1]);
            }
          }
        }
      }
      __syncthreads();
    }

    // epilogue: threshold per plane, beta-recombine, scale -> its own buffer
    float twoa = __fmul_rn(a, 2.0f);
    const float beta[MPL] = {8.0f / 15.0f, 4.0f / 15.0f, 2.0f / 15.0f, 1.0f / 15.0f};
#pragma unroll
    for (int r = 0; r < 4; ++r) {
#pragma unroll
      for (int c = 0; c < 4; ++c) {
        int b = bb + rowBase + r, o = ob + tx + 16 * c;
        float sv[4];
        unpack2(acc[r][c][0], sv[0], sv[1]);
        unpack2(acc[r][c][1], sv[2], sv[3]);
        float p = 0.0f;
#pragma unroll
        for (int m = 0; m < MPL; ++m) {
          float s = __fadd_rn(__fadd_rn(sv[m], bq[m * O_DIM + o]), nb[m * O_DIM + o]);
          p = __fadd_rn(p, (s > 0.5f) ? beta[m] : 0.0f);
        }
        gout[(size_t)b * O_DIM + o] = __fsub_rn(__fmul_rn(p, twoa), a);
      }
    }
  }
}

// ---------------- quantized LSTM pointwise tail ----------------
__device__ __forceinline__ float pactf(float x, float a) { return fminf(fmaxf(x, -a), a); }
__device__ __forceinline__ float quant8(float x, float r) {
  float xs = __fdiv_rn(x, r);
  xs = fminf(fmaxf(xs, -0.9921875f), 0.9921875f);
  return __fmul_rn(__fdiv_rn(rintf(__fmul_rn(xs, 128.0f)), 128.0f), r);
}

__global__ void k_lstm(const float* __restrict__ cx, float* __restrict__ out,
                       const float* a3, const float* a4, const float* a5, const float* a6,
                       const float* a7, const float* a8, const float* a9, const float* a10,
                       const float* a11) {
  int idx = blockIdx.x * blockDim.x + threadIdx.x;
  if (idx == 0) g_tile = 0u;          // reset work queue for the next graph replay
  if (idx >= B_DIM * H_DIM) return;
  int b = idx >> 10, h = idx & (H_DIM - 1);
  const float* g1 = g_gates1 + (size_t)b * O_DIM;
  const float* g2 = g_gates2 + (size_t)b * O_DIM;
  float gi = __fadd_rn(g1[h],        g2[h]);
  float gj = __fadd_rn(g1[h + 1024], g2[h + 1024]);
  float gf = __fadd_rn(g1[h + 2048], g2[h + 2048]);
  float go = __fadd_rn(g1[h + 3072], g2[h + 3072]);

  float v3 = *a3, v4 = *a4, v5 = *a5, v6 = *a6, v7 = *a7, v8 = *a8, v9 = *a9,
        v10 = *a10, v11 = *a11;
  float fg  = quant8(pactf(xla_logistic(gf), v3), v3);
  float ig  = quant8(pactf(xla_logistic(gi), v4), v4);
  float act = quant8(pactf(xla_tanh(gj), v5), v5);
  float og  = quant8(pactf(xla_logistic(go), v6), v6);
  float gated = quant8(pactf(__fmul_rn(cx[idx], fg), v7), v7);
  float actin = quant8(pactf(__fmul_rn(ig, act), v8), v8);
  float newc  = quant8(pactf(__fadd_rn(gated, actin), v9), v9);
  float actc  = quant8(pactf(xla_tanh(newc), v10), v10);
  float newh  = quant8(pactf(__fmul_rn(actc, og), v11), v11);
  out[idx] = newh;
  out[(size_t)B_DIM * H_DIM + idx] = newc;
}

// ---------------- host side ----------------
static void split2(const u32 k[2], u32 ka[2], u32 kb[2]) {
  threefry2x32(k[0], k[1], 0u, 0u, ka[0], ka[1]);
  threefry2x32(k[0], k[1], 0u, 1u, kb[0], kb[1]);
}

extern "C" void kernel_launch(void* const* d_in, const int* in_sizes, int n_in,
                              void* d_out, int out_size) {
  const float* input = (const float*)d_in[0];
  const float* hx    = (const float*)d_in[1];
  const float* cx    = (const float*)d_in[2];
  const float* wih   = (const float*)d_in[3];
  const float* whh   = (const float*)d_in[4];
  const float* bih   = (const float*)d_in[5];
  const float* bhh   = (const float*)d_in[6];
  const float* a1  = (const float*)d_in[7];
  const float* a3  = (const float*)d_in[8];
  const float* a4  = (const float*)d_in[9];
  const float* a5  = (const float*)d_in[10];
  const float* a6  = (const float*)d_in[11];
  const float* a7  = (const float*)d_in[12];
  const float* a8  = (const float*)d_in[13];
  const float* a9  = (const float*)d_in[14];
  const float* a10 = (const float*)d_in[15];
  const float* a11 = (const float*)d_in[16];

  // key(42) -> (k1,k2); k1 -> (kw_ih, kb_ih); k2 -> (kw_hh, kb_hh)   [fold-like]
  u32 root[2] = {0u, 42u}, K1[2], K2[2], KW1[2], KB1[2], KW2[2], KB2[2];
  split2(root, K1, K2);
  split2(K1, KW1, KB1);
  split2(K2, KW2, KB2);

  {
    dim3 g(512, 4);
    k_max4<<<g, 256>>>(wih, whh, bih, bhh);
  }

  k_build_w_all<<<(NW_IH + NW_HH + 255) / 256, 256>>>(wih, whh,
                                                      KW1[0], KW1[1], KW2[0], KW2[1]);
  {
    const int total = N_NIB_IN + N_NIB_HX + 2 * N_B;
    k_prep<<<(total + 255) / 256, 256>>>(input, hx, bih, bhh, a1, a11,
                                         KB1[0], KB1[1], KB2[0], KB2[1]);
  }

  // one persistent kernel: hh tiles (0..4095) then ih tiles (4096..8191)
  k_gemm_all<<<GRID_GEMM, 256>>>(a1, a11);

  k_lstm<<<(B_DIM * H_DIM + 255) / 256, 256>>>(cx, (float*)d_out,
                                               a3, a4, a5, a6, a7, a8, a9, a10, a11);
}

// round 16
// speedup vs baseline: 1.1988x; 1.0141x over previous
#include <cuda_runtime.h>
#include <cstdint>
#include <cstddef>

typedef unsigned int u32;
typedef unsigned long long u64;

// ---------------- problem dims ----------------
#define B_DIM 4096
#define I_DIM 256
#define H_DIM 1024
#define O_DIM 4096   // 4*H
#define MPL   4      // bit planes

#define NW_IH (MPL * I_DIM * O_DIM)   // 4,194,304
#define NW_HH (MPL * H_DIM * O_DIM)   // 16,777,216
#define N_B   (MPL * O_DIM)           // 16,384
#define N_NIB_IN (B_DIM * I_DIM)      // 1,048,576
#define N_NIB_HX (B_DIM * H_DIM)      // 4,194,304

// ---------------- static device scratch (no allocations allowed) ----------------
// Weff stored plane-interleaved: [K][O][MPL]
__device__ float   g_weff_ih[(size_t)I_DIM * O_DIM * MPL];      // 16 MB
__device__ float   g_weff_hh[(size_t)H_DIM * O_DIM * MPL];      // 64 MB
__device__ float   g_bq_ih[N_B];
__device__ float   g_nb_ih[N_B];
__device__ float   g_bq_hh[N_B];
__device__ float   g_nb_hh[N_B];
__device__ uint8_t g_nib_in[(size_t)N_NIB_IN];                  // 1 MB
__device__ uint8_t g_nib_hx[(size_t)N_NIB_HX];                  // 4 MB
__device__ float   g_gates1[(size_t)B_DIM * O_DIM];             // 64 MB (part1, ih)
__device__ float   g_gates2[(size_t)B_DIM * O_DIM];             // 64 MB (part2, hh)
// enc(-inf) = 0x007FFFFF; atomicMax is idempotent across graph replays
__device__ unsigned g_max[4] = {0x007FFFFFu, 0x007FFFFFu, 0x007FFFFFu, 0x007FFFFFu};
__device__ unsigned g_tile = 0u;     // work queue cursor; k_lstm resets for next call

// ---------------- threefry2x32 (JAX-exact) ----------------
__host__ __device__ __forceinline__ void threefry2x32(u32 k0, u32 k1, u32 x0, u32 x1,
                                                      u32 &o0, u32 &o1) {
  u32 ks2 = k0 ^ k1 ^ 0x1BD11BDAu;
  x0 += k0; x1 += k1;
#define TF_ROT(r) { x0 += x1; x1 = (x1 << (r)) | (x1 >> (32 - (r))); x1 ^= x0; }
  TF_ROT(13) TF_ROT(15) TF_ROT(26) TF_ROT(6)   x0 += k1;  x1 += ks2 + 1u;
  TF_ROT(17) TF_ROT(29) TF_ROT(16) TF_ROT(24)  x0 += ks2; x1 += k0 + 2u;
  TF_ROT(13) TF_ROT(15) TF_ROT(26) TF_ROT(6)   x0 += k0;  x1 += k1 + 3u;
  TF_ROT(17) TF_ROT(29) TF_ROT(16) TF_ROT(24)  x0 += k1;  x1 += ks2 + 4u;
  TF_ROT(13) TF_ROT(15) TF_ROT(26) TF_ROT(6)   x0 += ks2; x1 += k0 + 5u;
#undef TF_ROT
  o0 = x0; o1 = x1;
}

// ---------------- XLA-exact f32 transcendentals (unfused rn mul/add) --------
__device__ __forceinline__ float xla_log1p(float x) {
  float u = __fadd_rn(x, 1.0f);
  if (u == 1.0f) return x;
  return __fmul_rn(__fdiv_rn(x, __fsub_rn(u, 1.0f)), logf(u));
}

__device__ __forceinline__ float xla_erfinv(float x) {
  float w = -xla_log1p(__fmul_rn(__fmul_rn(-1.0f, x), x));
  float p;
  if (w < 5.0f) {
    w = __fsub_rn(w, 2.5f);
    p = 2.81022636e-08f;
    p = __fadd_rn(__fmul_rn(p, w), 3.43273939e-07f);
    p = __fadd_rn(__fmul_rn(p, w), -3.5233877e-06f);
    p = __fadd_rn(__fmul_rn(p, w), -4.39150654e-06f);
    p = __fadd_rn(__fmul_rn(p, w), 0.00021858087f);
    p = __fadd_rn(__fmul_rn(p, w), -0.00125372503f);
    p = __fadd_rn(__fmul_rn(p, w), -0.00417768164f);
    p = __fadd_rn(__fmul_rn(p, w), 0.246640727f);
    p = __fadd_rn(__fmul_rn(p, w), 1.50140941f);
  } else {
    w = __fsub_rn(sqrtf(w), 3.0f);
    p = -0.000200214257f;
    p = __fadd_rn(__fmul_rn(p, w), 0.000100950558f);
    p = __fadd_rn(__fmul_rn(p, w), 0.00134934322f);
    p = __fadd_rn(__fmul_rn(p, w), -0.00367342844f);
    p = __fadd_rn(__fmul_rn(p, w), 0.00573950773f);
    p = __fadd_rn(__fmul_rn(p, w), -0.0076224613f);
    p = __fadd_rn(__fmul_rn(p, w), 0.00943887047f);
    p = __fadd_rn(__fmul_rn(p, w), 1.00167406f);
    p = __fadd_rn(__fmul_rn(p, w), 2.83297682f);
  }
  return __fmul_rn(p, x);
}

__device__ __forceinline__ float xla_tanh(float x) {
  float ax = fabsf(x);
  if (ax < 0.0004f) return x;
  float xc = fminf(fmaxf(x, -7.90531110763549805f), 7.90531110763549805f);
  float x2 = __fmul_rn(xc, xc);
  float p = -2.76076847742355e-16f;
  p = __fadd_rn(__fmul_rn(p, x2), 2.00018790482477e-13f);
  p = __fadd_rn(__fmul_rn(p, x2), -8.60467152213735e-11f);
  p = __fadd_rn(__fmul_rn(p, x2), 5.12229709037114e-08f);
  p = __fadd_rn(__fmul_rn(p, x2), 1.48572235717979e-05f);
  p = __fadd_rn(__fmul_rn(p, x2), 6.37261928875436e-04f);
  p = __fadd_rn(__fmul_rn(p, x2), 4.89352455891786e-03f);
  p = __fmul_rn(p, xc);
  float q = 1.19825839466702e-06f;
  q = __fadd_rn(__fmul_rn(q, x2), 1.18534705686654e-04f);
  q = __fadd_rn(__fmul_rn(q, x2), 2.26843463243900e-03f);
  q = __fadd_rn(__fmul_rn(q, x2), 4.89352518554385e-03f);
  return __fdiv_rn(p, q);
}

__device__ __forceinline__ float xla_logistic(float x) {
  return __fadd_rn(0.5f, __fmul_rn(0.5f, xla_tanh(__fmul_rn(0.5f, x))));
}

// bits -> N(0,1) exactly as jax.random.normal (float32 path)
__device__ __forceinline__ float bits_to_normal(u32 bits) {
  float u = __uint_as_float((bits >> 9) | 0x3F800000u) - 1.0f;   // [0,1)
  const float lo = __uint_as_float(0xBF7FFFFFu);                 // nextafter(-1,0)
  float v = __fadd_rn(__fmul_rn(u, 2.0f), lo);
  v = fmaxf(v, lo);
  return __fmul_rn(__uint_as_float(0x3FB504F3u) /*sqrt2*/, xla_erfinv(v));
}

// partitionable threefry random_bits: bits[j] = o0 ^ o1 of TF(key, 0, j)
__device__ __forceinline__ u32 jax_bits32(u32 k0, u32 k1, u32 j) {
  u32 o0, o1; threefry2x32(k0, k1, 0u, j, o0, o1);
  return o0 ^ o1;
}

// ---------------- float max encoding for atomicMax ----------------
__device__ __forceinline__ unsigned fenc(float f) {
  unsigned u = __float_as_uint(f);
  return (u & 0x80000000u) ? ~u : (u | 0x80000000u);
}
__device__ __forceinline__ float fdec(unsigned u) {
  return (u & 0x80000000u) ? __uint_as_float(u & 0x7FFFFFFFu) : __uint_as_float(~u);
}

// one launch, 4 reductions (y selects the array)
__global__ void k_max4(const float* __restrict__ wih, const float* __restrict__ whh,
                       const float* __restrict__ bih, const float* __restrict__ bhh) {
  int slot = blockIdx.y;
  const float* x = (slot == 0) ? wih : (slot == 1) ? whh : (slot == 2) ? bih : bhh;
  int n = (slot == 0) ? NW_IH : (slot == 1) ? NW_HH : N_B;
  float m = -__int_as_float(0x7F800000);
  for (int i = blockIdx.x * blockDim.x + threadIdx.x; i < n; i += gridDim.x * blockDim.x)
    m = fmaxf(m, x[i]);
#pragma unroll
  for (int o = 16; o; o >>= 1) m = fmaxf(m, __shfl_xor_sync(0xFFFFFFFFu, m, o));
  if ((threadIdx.x & 31) == 0) atomicMax(&g_max[slot], fenc(m));
}

// quant(x, 8, 1.0) for weights
__device__ __forceinline__ float quant_w(float x) {
  float xs = fminf(fmaxf(x, -0.9921875f), 0.9921875f);
  return __fmul_rn(__fdiv_rn(rintf(__fmul_rn(xs, 128.0f)), 128.0f), 1.0f);
}

// Weff[k][o][m] = quant(W[m][k][o]) + normal(ctr = src linear)*wmax*0.1
// Both matrices in one launch: j < NW_IH -> ih, else hh.
__global__ void k_build_w_all(const float* __restrict__ Wih, const float* __restrict__ Whh,
                              u32 ka0, u32 ka1, u32 kb0, u32 kb1) {
  int j = blockIdx.x * blockDim.x + threadIdx.x;
  const float* W; float* dst; int K; u32 kk0, kk1; float wmax; int jj;
  if (j < NW_IH) {
    W = Wih; dst = g_weff_ih; K = I_DIM; kk0 = ka0; kk1 = ka1;
    wmax = fdec(g_max[0]); jj = j;
  } else {
    jj = j - NW_IH;
    if (jj >= NW_HH) return;
    W = Whh; dst = g_weff_hh; K = H_DIM; kk0 = kb0; kk1 = kb1;
    wmax = fdec(g_max[1]);
  }
  int k = jj >> 14;                 // O_DIM*MPL = 16384
  int rem = jj & 16383;
  int o = rem >> 2, m = rem & 3;
  u32 src = (u32)((m * K + k) * O_DIM + o);        // source linear = PRNG counter
  float nr = bits_to_normal(jax_bits32(kk0, kk1, src));
  dst[jj] = __fadd_rn(quant_w(W[src]), __fmul_rn(__fmul_rn(nr, wmax), 0.1f));
}

// nibbles (both branches) + biases (both branches), one launch.
__global__ void k_prep(const float* __restrict__ input, const float* __restrict__ hx,
                       const float* __restrict__ Bih, const float* __restrict__ Bhh,
                       const float* __restrict__ a1P, const float* __restrict__ a11P,
                       u32 kbi0, u32 kbi1, u32 kbh0, u32 kbh1) {
  int i = blockIdx.x * blockDim.x + threadIdx.x;
  float a1 = *a1P;
  if (i < N_NIB_IN) {
    float a = a1, off = a1;
    float t = __fdiv_rn(__fadd_rn(fminf(fmaxf(input[i], -a), a), off), __fmul_rn(a, 2.0f));
    g_nib_in[i] = (uint8_t)(((int)rintf(__fmul_rn(15.0f, t))) & 15);
  } else if (i < N_NIB_IN + N_NIB_HX) {
    int idx = i - N_NIB_IN;
    float a = *a11P, off = a1;                    // '+ a1' quirk preserved
    float t = __fdiv_rn(__fadd_rn(fminf(fmaxf(hx[idx], -a), a), off), __fmul_rn(a, 2.0f));
    g_nib_hx[idx] = (uint8_t)(((int)rintf(__fmul_rn(15.0f, t))) & 15);
  } else if (i < N_NIB_IN + N_NIB_HX + N_B) {
    int j = i - N_NIB_IN - N_NIB_HX;
    float bmax = fdec(g_max[2]);
    g_bq_ih[j] = quant_w(Bih[j]);
    g_nb_ih[j] = __fmul_rn(__fmul_rn(bits_to_normal(jax_bits32(kbi0, kbi1, (u32)j)), bmax), 0.1f);
  } else {
    int j = i - N_NIB_IN - N_NIB_HX - N_B;
    if (j >= N_B) return;
    float bmax = fdec(g_max[3]);
    g_bq_hh[j] = quant_w(Bhh[j]);
    g_nb_hh[j] = __fmul_rn(__fmul_rn(bits_to_normal(jax_bits32(kbh0, kbh1, (u32)j)), bmax), 0.1f);
  }
}

// ---------------- persistent GEMM (both branches, one kernel) ----------------
// fma.rn.f32x2 lanes = plane pairs; per-lane acc = rn(w*mask + acc).
// Masks via LOP3-pred + SELP with PER-S IMMEDIATE bit positions (no shifts):
// exact constants 0x3F800000 / 0 -> bit-identical accumulation chain.
#define BM 64
#define BN 64
#define KC 32
#define N_TILES_HH 4096
#define N_TILES_ALL 8192
#define GRID_GEMM 304               // GB300: 152 SMs x 2 blocks/SM

__device__ __forceinline__ void fma2(u64 &acc, u64 w, u64 m) {
  asm volatile("fma.rn.f32x2 %0, %1, %2, %0;" : "+l"(acc) : "l"(w), "l"(m));
}
__device__ __forceinline__ void lds_v2u64(u64 &a, u64 &b, u32 addr) {
  asm volatile("ld.shared.v2.b64 {%0,%1}, [%2];" : "=l"(a), "=l"(b) : "r"(addr));
}
__device__ __forceinline__ void unpack2(u64 v, float &lo, float &hi) {
  u32 l, h;
  asm volatile("mov.b64 {%0,%1}, %2;" : "=r"(l), "=r"(h) : "l"(v));
  lo = __uint_as_float(l); hi = __uint_as_float(h);
}

// two masks from bits bitA (lo word) / bitB (hi word) of av; bitA/bitB are
// compile-time constants after unrolling -> LOP3-pred immediates, no shifts
__device__ __forceinline__ u64 mask2(u32 av, u32 bitA, u32 bitB) {
  u64 out;
  asm("{\n\t"
      ".reg .pred pa, pb;\n\t"
      ".reg .b32 ta, tb, ma, mb;\n\t"
      "and.b32 ta, %1, %2;\n\t"
      "and.b32 tb, %1, %3;\n\t"
      "setp.ne.u32 pa, ta, 0;\n\t"
      "setp.ne.u32 pb, tb, 0;\n\t"
      "selp.b32 ma, 0x3F800000, 0, pa;\n\t"
      "selp.b32 mb, 0x3F800000, 0, pb;\n\t"
      "mov.b64 %0, {ma, mb};\n\t"
      "}" : "=l"(out) : "r"(av), "r"(bitA), "r"(bitB));
  return out;
}

__launch_bounds__(256, 2)
__global__ void k_gemm_all(const float* __restrict__ a1P, const float* __restrict__ a11P) {
  __shared__ __align__(16) float sW[KC][BN * MPL];   // 32 KB, [k][o*4+m]
  __shared__ __align__(16) u32 sAT[KC / 4][68];      // transposed A, padded rows
  __shared__ u32 sTile;

  int tid = threadIdx.x;
  int tx = tid & 15, ty = tid >> 4;
  int rowBase = ty * 4;

  u32 sWb = (u32)__cvta_generic_to_shared(sW);

  while (true) {
    if (tid == 0) sTile = atomicAdd(&g_tile, 1u);
    __syncthreads();                 // orders prev-tile smem reuse
    u32 t = sTile;
    if (t >= N_TILES_ALL) break;

    // hh tiles first (big), then ih (small) for a short ragged tail
    bool hh = (t < N_TILES_HH);
    u32 t2 = hh ? t : (t - N_TILES_HH);
    int K = hh ? H_DIM : I_DIM;
    const float* __restrict__ Wg = hh ? g_weff_hh : g_weff_ih;   // [K][O][MPL]
    const float* __restrict__ bq = hh ? g_bq_hh : g_bq_ih;
    const float* __restrict__ nb = hh ? g_nb_hh : g_nb_ih;
    const uint8_t* __restrict__ nibp = hh ? g_nib_hx : g_nib_in;
    float* __restrict__ gout = hh ? g_gates2 : g_gates1;
    float a = hh ? *a11P : *a1P;

    int ob = (int)(t2 & 63) * BN;
    int bb = (int)(t2 >> 6) * BM;

    u64 acc[4][4][2];   // [row][col][plane-pair]
#pragma unroll
    for (int r = 0; r < 4; ++r)
#pragma unroll
      for (int c = 0; c < 4; ++c) { acc[r][c][0] = 0ull; acc[r][c][1] = 0ull; }

    for (int k0 = 0; k0 < K; k0 += KC) {
#pragma unroll
      for (int tt = 0; tt < 2; ++tt) {            // A tile: transposed [k4][row]
        int idx = tid + tt * 256;
        int r = idx >> 3, k4 = idx & 7;
        sAT[k4][r] = *(const u32*)(nibp + (size_t)(bb + r) * K + k0 + k4 * 4);
      }
#pragma unroll
      for (int tt = 0; tt < 8; ++tt) {            // W tile: 2048 contiguous float4
        int idx = tid + tt * 256;
        int k = idx >> 6, w4 = idx & 63;
        *(float4*)&sW[k][w4 * 4] =
            *(const float4*)(Wg + ((size_t)(k0 + k) * O_DIM + ob) * MPL + w4 * 4);
      }
      __syncthreads();

#pragma unroll 4
      for (int k4 = 0; k4 < KC / 4; ++k4) {
        uint4 av4 = *(const uint4*)&sAT[k4][rowBase];   // one LDS.128, 4 rows
        u32 av[4] = {av4.x, av4.y, av4.z, av4.w};
#pragma unroll
        for (int s = 0; s < 4; ++s) {
          int k = k4 * 4 + s;
          const u32 b3 = 8u << (8 * s), b2 = 4u << (8 * s);
          const u32 b1 = 2u << (8 * s), b0 = 1u << (8 * s);
          u64 mk[4][2];
#pragma unroll
          for (int r = 0; r < 4; ++r) {
            mk[r][0] = mask2(av[r], b3, b2);
            mk[r][1] = mask2(av[r], b1, b0);
          }
#pragma unroll
          for (int c = 0; c < 4; ++c) {
            u64 w0, w1;
            u32 wad = sWb + (u32)(k * (BN * MPL * 4)) + (u32)((tx + 16 * c) * 16);
            lds_v2u64(w0, w1, wad);
#pragma unroll
            for (int r = 0; r < 4; ++r) {
              fma2(acc[r][c][0], w0, mk[r][0]);
              fma2(acc[r][c][1], w1, mk[r][1]);
            }
          }
        }
      }
      __syncthreads();
    }

    // epilogue: threshold per plane, beta-recombine, scale -> its own buffer
    float twoa = __fmul_rn(a, 2.0f);
    const float beta[MPL] = {8.0f / 15.0f, 4.0f / 15.0f, 2.0f / 15.0f, 1.0f / 15.0f};
#pragma unroll
    for (int r = 0; r < 4; ++r) {
#pragma unroll
      for (int c = 0; c < 4; ++c) {
        int b = bb + rowBase + r, o = ob + tx + 16 * c;
        float sv[4];
        unpack2(acc[r][c][0], sv[0], sv[1]);
        unpack2(acc[r][c][1], sv[2], sv[3]);
        float p = 0.0f;
#pragma unroll
        for (int m = 0; m < MPL; ++m) {
          float s = __fadd_rn(__fadd_rn(sv[m], bq[m * O_DIM + o]), nb[m * O_DIM + o]);
          p = __fadd_rn(p, (s > 0.5f) ? beta[m] : 0.0f);
        }
        gout[(size_t)b * O_DIM + o] = __fsub_rn(__fmul_rn(p, twoa), a);
      }
    }
  }
}

// ---------------- quantized LSTM pointwise tail ----------------
__device__ __forceinline__ float pactf(float x, float a) { return fminf(fmaxf(x, -a), a); }
__device__ __forceinline__ float quant8(float x, float r) {
  float xs = __fdiv_rn(x, r);
  xs = fminf(fmaxf(xs, -0.9921875f), 0.9921875f);
  return __fmul_rn(__fdiv_rn(rintf(__fmul_rn(xs, 128.0f)), 128.0f), r);
}

__global__ void k_lstm(const float* __restrict__ cx, float* __restrict__ out,
                       const float* a3, const float* a4, const float* a5, const float* a6,
                       const float* a7, const float* a8, const float* a9, const float* a10,
                       const float* a11) {
  int idx = blockIdx.x * blockDim.x + threadIdx.x;
  if (idx == 0) g_tile = 0u;          // reset work queue for the next graph replay
  if (idx >= B_DIM * H_DIM) return;
  int b = idx >> 10, h = idx & (H_DIM - 1);
  const float* g1 = g_gates1 + (size_t)b * O_DIM;
  const float* g2 = g_gates2 + (size_t)b * O_DIM;
  float gi = __fadd_rn(g1[h],        g2[h]);
  float gj = __fadd_rn(g1[h + 1024], g2[h + 1024]);
  float gf = __fadd_rn(g1[h + 2048], g2[h + 2048]);
  float go = __fadd_rn(g1[h + 3072], g2[h + 3072]);

  float v3 = *a3, v4 = *a4, v5 = *a5, v6 = *a6, v7 = *a7, v8 = *a8, v9 = *a9,
        v10 = *a10, v11 = *a11;
  float fg  = quant8(pactf(xla_logistic(gf), v3), v3);
  float ig  = quant8(pactf(xla_logistic(gi), v4), v4);
  float act = quant8(pactf(xla_tanh(gj), v5), v5);
  float og  = quant8(pactf(xla_logistic(go), v6), v6);
  float gated = quant8(pactf(__fmul_rn(cx[idx], fg), v7), v7);
  float actin = quant8(pactf(__fmul_rn(ig, act), v8), v8);
  float newc  = quant8(pactf(__fadd_rn(gated, actin), v9), v9);
  float actc  = quant8(pactf(xla_tanh(newc), v10), v10);
  float newh  = quant8(pactf(__fmul_rn(actc, og), v11), v11);
  out[idx] = newh;
  out[(size_t)B_DIM * H_DIM + idx] = newc;
}

// ---------------- host side ----------------
static void split2(const u32 k[2], u32 ka[2], u32 kb[2]) {
  threefry2x32(k[0], k[1], 0u, 0u, ka[0], ka[1]);
  threefry2x32(k[0], k[1], 0u, 1u, kb[0], kb[1]);
}

extern "C" void kernel_launch(void* const* d_in, const int* in_sizes, int n_in,
                              void* d_out, int out_size) {
  const float* input = (const float*)d_in[0];
  const float* hx    = (const float*)d_in[1];
  const float* cx    = (const float*)d_in[2];
  const float* wih   = (const float*)d_in[3];
  const float* whh   = (const float*)d_in[4];
  const float* bih   = (const float*)d_in[5];
  const float* bhh   = (const float*)d_in[6];
  const float* a1  = (const float*)d_in[7];
  const float* a3  = (const float*)d_in[8];
  const float* a4  = (const float*)d_in[9];
  const float* a5  = (const float*)d_in[10];
  const float* a6  = (const float*)d_in[11];
  const float* a7  = (const float*)d_in[12];
  const float* a8  = (const float*)d_in[13];
  const float* a9  = (const float*)d_in[14];
  const float* a10 = (const float*)d_in[15];
  const float* a11 = (const float*)d_in[16];

  // key(42) -> (k1,k2); k1 -> (kw_ih, kb_ih); k2 -> (kw_hh, kb_hh)   [fold-like]
  u32 root[2] = {0u, 42u}, K1[2], K2[2], KW1[2], KB1[2], KW2[2], KB2[2];
  split2(root, K1, K2);
  split2(K1, KW1, KB1);
  split2(K2, KW2, KB2);

  {
    dim3 g(512, 4);
    k_max4<<<g, 256>>>(wih, whh, bih, bhh);
  }

  k_build_w_all<<<(NW_IH + NW_HH + 255) / 256, 256>>>(wih, whh,
                                                      KW1[0], KW1[1], KW2[0], KW2[1]);
  {
    const int total = N_NIB_IN + N_NIB_HX + 2 * N_B;
    k_prep<<<(total + 255) / 256, 256>>>(input, hx, bih, bhh, a1, a11,
                                         KB1[0], KB1[1], KB2[0], KB2[1]);
  }

  // one persistent kernel: hh tiles (0..4095) then ih tiles (4096..8191)
  k_gemm_all<<<GRID_GEMM, 256>>>(a1, a11);

  k_lstm<<<(B_DIM * H_DIM + 255) / 256, 256>>>(cx, (float*)d_out,
                                               a3, a4, a5, a6, a7, a8, a9, a10, a11);
}